// round 4
// baseline (speedup 1.0000x reference)
#include <cuda_runtime.h>

// SelfNorm collapsed: out = x*std_w + mean*(mean_w - std_w), per (b,c) row.
// One CTA (512 threads) per row. Row held in REGISTERS (2 float4/thread),
// read from DRAM exactly once (streaming). Single barrier; all threads
// compute the tiny MLPs redundantly from smem-staged weights.

#define HW 3136          // 56*56
#define F4 784           // HW/4 = 512 + 272
#define NTHREADS 512
#define NWARPS 16
#define EPS 1e-5f

// smem weight layout offsets
#define W1M 0
#define B1M 32
#define W2M 48
#define B2M 64
#define W1S 65
#define B1S 97
#define W2S 113
#define B2S 129
#define NW  130

__device__ __forceinline__ float tiny_mlp_sm(float mean, float std,
                                             const float* __restrict__ w,
                                             int w1, int b1, int w2, int b2) {
    float z = w[b2];
    #pragma unroll
    for (int o = 0; o < 16; o++) {
        float h = fmaf(w[w1 + 2 * o], mean,
                  fmaf(w[w1 + 2 * o + 1], std, w[b1 + o]));
        h = fmaxf(h, 0.0f);
        z = fmaf(w[w2 + o], h, z);
    }
    return 1.0f / (1.0f + __expf(-z));
}

__global__ void __launch_bounds__(NTHREADS, 4)
selfnorm_kernel(const float4* __restrict__ x,
                const float* __restrict__ W1m, const float* __restrict__ b1m,
                const float* __restrict__ W2m, const float* __restrict__ b2m,
                const float* __restrict__ W1s, const float* __restrict__ b1s,
                const float* __restrict__ W2s, const float* __restrict__ b2s,
                float4* __restrict__ out) {
    __shared__ float ps[NWARPS], psq[NWARPS];
    __shared__ float w[NW];

    const int t    = threadIdx.x;
    const int lane = t & 31;
    const int wid  = t >> 5;

    const float4* __restrict__ xr   = x   + (size_t)blockIdx.x * F4;
    float4*       __restrict__ orow = out + (size_t)blockIdx.x * F4;

    // ---- Stage MLP weights into smem (covered by the single barrier) ----
    if (t < NW) {
        float v;
        if      (t < 32)  v = W1m[t];
        else if (t < 48)  v = b1m[t - 32];
        else if (t < 64)  v = W2m[t - 48];
        else if (t == 64) v = b2m[0];
        else if (t < 97)  v = W1s[t - 65];
        else if (t < 113) v = b1s[t - 97];
        else if (t < 129) v = W2s[t - 113];
        else              v = b2s[0];
        w[t] = v;
    }

    // ---- Load row into registers (streaming), accumulate stats ----
    const bool rem = (t < (F4 - NTHREADS));   // 272
    float4 a0 = __ldcs(xr + t);
    float4 a1;
    if (rem) a1 = __ldcs(xr + NTHREADS + t);

    float s  = a0.x + a0.y + a0.z + a0.w;
    float sq = 0.0f;
    sq = fmaf(a0.x, a0.x, sq); sq = fmaf(a0.y, a0.y, sq);
    sq = fmaf(a0.z, a0.z, sq); sq = fmaf(a0.w, a0.w, sq);
    if (rem) {
        s += a1.x + a1.y + a1.z + a1.w;
        sq = fmaf(a1.x, a1.x, sq); sq = fmaf(a1.y, a1.y, sq);
        sq = fmaf(a1.z, a1.z, sq); sq = fmaf(a1.w, a1.w, sq);
    }

    // ---- Warp reduce, one barrier ----
    #pragma unroll
    for (int o = 16; o > 0; o >>= 1) {
        s  += __shfl_xor_sync(0xffffffffu, s,  o);
        sq += __shfl_xor_sync(0xffffffffu, sq, o);
    }
    if (lane == 0) { ps[wid] = s; psq[wid] = sq; }
    __syncthreads();

    // ---- Final sum + redundant MLPs on every thread ----
    float ts = 0.0f, tsq = 0.0f;
    #pragma unroll
    for (int i = 0; i < NWARPS; i++) { ts += ps[i]; tsq += psq[i]; }

    const float n = (float)HW;
    float mean = ts / n;
    float var  = (tsq - n * mean * mean) / (n - 1.0f);
    var = fmaxf(var, 0.0f);
    float std = sqrtf(var + EPS);

    float mean_w = tiny_mlp_sm(mean, std, w, W1M, B1M, W2M, B2M);
    float std_w  = tiny_mlp_sm(mean, std, w, W1S, B1S, W2S, B2S);

    const float alpha = std_w;
    const float beta  = mean * (mean_w - std_w);

    // ---- Transform registers, streaming store ----
    float4 r;
    r.x = fmaf(a0.x, alpha, beta);
    r.y = fmaf(a0.y, alpha, beta);
    r.z = fmaf(a0.z, alpha, beta);
    r.w = fmaf(a0.w, alpha, beta);
    __stcs(orow + t, r);
    if (rem) {
        r.x = fmaf(a1.x, alpha, beta);
        r.y = fmaf(a1.y, alpha, beta);
        r.z = fmaf(a1.z, alpha, beta);
        r.w = fmaf(a1.w, alpha, beta);
        __stcs(orow + NTHREADS + t, r);
    }
}

extern "C" void kernel_launch(void* const* d_in, const int* in_sizes, int n_in,
                              void* d_out, int out_size) {
    const float4* x  = (const float4*)d_in[0];
    const float* W1m = (const float*)d_in[1];
    const float* b1m = (const float*)d_in[2];
    const float* W2m = (const float*)d_in[3];
    const float* b2m = (const float*)d_in[4];
    const float* W1s = (const float*)d_in[5];
    const float* b1s = (const float*)d_in[6];
    const float* W2s = (const float*)d_in[7];
    const float* b2s = (const float*)d_in[8];
    float4* out = (float4*)d_out;

    const int rows = 32 * 256;  // B * C = 8192 CTAs, one row each
    selfnorm_kernel<<<rows, NTHREADS>>>(x, W1m, b1m, W2m, b2m,
                                        W1s, b1s, W2s, b2s, out);
}

// round 5
// speedup vs baseline: 1.4202x; 1.4202x over previous
#include <cuda_runtime.h>

// SelfNorm collapsed: out = x*std_w + mean*(mean_w - std_w), per (b,c) row.
// One CTA (256 thr) per row; row held in registers; x read from DRAM once.
// MLP weights staged into __constant__ memory by graph-capturable D2D
// memcpys, so the redundant per-thread MLP costs zero L1tex wavefronts.
// Single barrier, no serial section.

#define HW 3136          // 56*56
#define F4 784           // HW/4 = 3*256 + 16
#define NTHREADS 256
#define EPS 1e-5f

// constant weight bank: [W1m(32) b1m(16) W2m(16) b2m(1) W1s(32) b1s(16) W2s(16) b2s(1)]
#define OFF_W1M 0
#define OFF_B1M 32
#define OFF_W2M 48
#define OFF_B2M 64
#define OFF_W1S 65
#define OFF_B1S 97
#define OFF_W2S 113
#define OFF_B2S 129
__constant__ float cw[130];

__device__ __forceinline__ float tiny_mlp_c(float mean, float std,
                                            int w1, int b1, int w2, int b2) {
    float z = cw[b2];
    #pragma unroll
    for (int o = 0; o < 16; o++) {
        float h = fmaf(cw[w1 + 2 * o], mean,
                  fmaf(cw[w1 + 2 * o + 1], std, cw[b1 + o]));
        h = fmaxf(h, 0.0f);
        z = fmaf(cw[w2 + o], h, z);
    }
    return 1.0f / (1.0f + __expf(-z));
}

__global__ void __launch_bounds__(NTHREADS)
selfnorm_kernel(const float4* __restrict__ x, float4* __restrict__ out) {
    __shared__ float ps[8], psq[8];

    const int t    = threadIdx.x;
    const int lane = t & 31;
    const int wid  = t >> 5;

    const float4* __restrict__ xr   = x   + (size_t)blockIdx.x * F4;
    float4*       __restrict__ orow = out + (size_t)blockIdx.x * F4;

    // ---- Load whole row into registers (streaming), accumulate stats ----
    const bool rem = (t < 16);   // 784 - 3*256
    float4 a0 = __ldcs(xr + t);
    float4 a1 = __ldcs(xr + t + 256);
    float4 a2 = __ldcs(xr + t + 512);
    float4 a3;
    if (rem) a3 = __ldcs(xr + 768 + t);

    float s  = a0.x + a0.y + a0.z + a0.w;
    float sq = 0.0f;
    sq = fmaf(a0.x, a0.x, sq); sq = fmaf(a0.y, a0.y, sq);
    sq = fmaf(a0.z, a0.z, sq); sq = fmaf(a0.w, a0.w, sq);
    s += a1.x + a1.y + a1.z + a1.w;
    sq = fmaf(a1.x, a1.x, sq); sq = fmaf(a1.y, a1.y, sq);
    sq = fmaf(a1.z, a1.z, sq); sq = fmaf(a1.w, a1.w, sq);
    s += a2.x + a2.y + a2.z + a2.w;
    sq = fmaf(a2.x, a2.x, sq); sq = fmaf(a2.y, a2.y, sq);
    sq = fmaf(a2.z, a2.z, sq); sq = fmaf(a2.w, a2.w, sq);
    if (rem) {
        s += a3.x + a3.y + a3.z + a3.w;
        sq = fmaf(a3.x, a3.x, sq); sq = fmaf(a3.y, a3.y, sq);
        sq = fmaf(a3.z, a3.z, sq); sq = fmaf(a3.w, a3.w, sq);
    }

    // ---- Warp reduce, one barrier ----
    #pragma unroll
    for (int o = 16; o > 0; o >>= 1) {
        s  += __shfl_xor_sync(0xffffffffu, s,  o);
        sq += __shfl_xor_sync(0xffffffffu, sq, o);
    }
    if (lane == 0) { ps[wid] = s; psq[wid] = sq; }
    __syncthreads();

    // ---- Every thread: final sum + MLPs from constant memory ----
    float ts = 0.0f, tsq = 0.0f;
    #pragma unroll
    for (int i = 0; i < 8; i++) { ts += ps[i]; tsq += psq[i]; }

    const float n = (float)HW;
    float mean = ts / n;
    float var  = (tsq - n * mean * mean) / (n - 1.0f);
    var = fmaxf(var, 0.0f);
    float std = sqrtf(var + EPS);

    float mean_w = tiny_mlp_c(mean, std, OFF_W1M, OFF_B1M, OFF_W2M, OFF_B2M);
    float std_w  = tiny_mlp_c(mean, std, OFF_W1S, OFF_B1S, OFF_W2S, OFF_B2S);

    const float alpha = std_w;
    const float beta  = mean * (mean_w - std_w);

    // ---- Transform registers, streaming store ----
    float4 r;
    r.x = fmaf(a0.x, alpha, beta);
    r.y = fmaf(a0.y, alpha, beta);
    r.z = fmaf(a0.z, alpha, beta);
    r.w = fmaf(a0.w, alpha, beta);
    __stcs(orow + t, r);
    r.x = fmaf(a1.x, alpha, beta);
    r.y = fmaf(a1.y, alpha, beta);
    r.z = fmaf(a1.z, alpha, beta);
    r.w = fmaf(a1.w, alpha, beta);
    __stcs(orow + t + 256, r);
    r.x = fmaf(a2.x, alpha, beta);
    r.y = fmaf(a2.y, alpha, beta);
    r.z = fmaf(a2.z, alpha, beta);
    r.w = fmaf(a2.w, alpha, beta);
    __stcs(orow + t + 512, r);
    if (rem) {
        r.x = fmaf(a3.x, alpha, beta);
        r.y = fmaf(a3.y, alpha, beta);
        r.z = fmaf(a3.z, alpha, beta);
        r.w = fmaf(a3.w, alpha, beta);
        __stcs(orow + 768 + t, r);
    }
}

extern "C" void kernel_launch(void* const* d_in, const int* in_sizes, int n_in,
                              void* d_out, int out_size) {
    const float4* x = (const float4*)d_in[0];
    float4* out = (float4*)d_out;

    // Stage MLP weights into constant memory (D2D memcpy nodes; capturable).
    cudaMemcpyToSymbolAsync(cw, d_in[1], 32 * sizeof(float), OFF_W1M * sizeof(float),
                            cudaMemcpyDeviceToDevice, 0);
    cudaMemcpyToSymbolAsync(cw, d_in[2], 16 * sizeof(float), OFF_B1M * sizeof(float),
                            cudaMemcpyDeviceToDevice, 0);
    cudaMemcpyToSymbolAsync(cw, d_in[3], 16 * sizeof(float), OFF_W2M * sizeof(float),
                            cudaMemcpyDeviceToDevice, 0);
    cudaMemcpyToSymbolAsync(cw, d_in[4],  1 * sizeof(float), OFF_B2M * sizeof(float),
                            cudaMemcpyDeviceToDevice, 0);
    cudaMemcpyToSymbolAsync(cw, d_in[5], 32 * sizeof(float), OFF_W1S * sizeof(float),
                            cudaMemcpyDeviceToDevice, 0);
    cudaMemcpyToSymbolAsync(cw, d_in[6], 16 * sizeof(float), OFF_B1S * sizeof(float),
                            cudaMemcpyDeviceToDevice, 0);
    cudaMemcpyToSymbolAsync(cw, d_in[7], 16 * sizeof(float), OFF_W2S * sizeof(float),
                            cudaMemcpyDeviceToDevice, 0);
    cudaMemcpyToSymbolAsync(cw, d_in[8],  1 * sizeof(float), OFF_B2S * sizeof(float),
                            cudaMemcpyDeviceToDevice, 0);

    const int rows = 32 * 256;  // B * C = 8192 CTAs, one row each
    selfnorm_kernel<<<rows, NTHREADS>>>(x, out);
}

// round 6
// speedup vs baseline: 1.8306x; 1.2889x over previous
#include <cuda_runtime.h>

// SelfNorm collapsed: out = x*std_w + mean*(mean_w - std_w), per (b,c) row.
// One CTA (256 thr) per row; row held in registers; x read from DRAM once
// (streaming). Single barrier. Both tiny MLPs computed lane-parallel inside
// each warp (lane<16: mean-MLP unit, lane>=16: std-MLP unit) with shuffle
// reduction — zero smem/const staging, zero extra graph nodes.

#define HW 3136          // 56*56
#define F4 784           // HW/4 = 3*256 + 16
#define NTHREADS 256
#define EPS 1e-5f

__global__ void __launch_bounds__(NTHREADS)
selfnorm_kernel(const float4* __restrict__ x,
                const float* __restrict__ W1m, const float* __restrict__ b1m,
                const float* __restrict__ W2m, const float* __restrict__ b2m,
                const float* __restrict__ W1s, const float* __restrict__ b1s,
                const float* __restrict__ W2s, const float* __restrict__ b2s,
                float4* __restrict__ out) {
    __shared__ float ps[8], psq[8];

    const int t    = threadIdx.x;
    const int lane = t & 31;
    const int wid  = t >> 5;

    const float4* __restrict__ xr   = x   + (size_t)blockIdx.x * F4;
    float4*       __restrict__ orow = out + (size_t)blockIdx.x * F4;

    // ---- Load whole row into registers (streaming), accumulate stats ----
    const bool rem = (t < 16);   // 784 - 3*256
    float4 a0 = __ldcs(xr + t);
    float4 a1 = __ldcs(xr + t + 256);
    float4 a2 = __ldcs(xr + t + 512);
    float4 a3;
    if (rem) a3 = __ldcs(xr + 768 + t);

    float s  = a0.x + a0.y + a0.z + a0.w;
    float sq = 0.0f;
    sq = fmaf(a0.x, a0.x, sq); sq = fmaf(a0.y, a0.y, sq);
    sq = fmaf(a0.z, a0.z, sq); sq = fmaf(a0.w, a0.w, sq);
    s += a1.x + a1.y + a1.z + a1.w;
    sq = fmaf(a1.x, a1.x, sq); sq = fmaf(a1.y, a1.y, sq);
    sq = fmaf(a1.z, a1.z, sq); sq = fmaf(a1.w, a1.w, sq);
    s += a2.x + a2.y + a2.z + a2.w;
    sq = fmaf(a2.x, a2.x, sq); sq = fmaf(a2.y, a2.y, sq);
    sq = fmaf(a2.z, a2.z, sq); sq = fmaf(a2.w, a2.w, sq);
    if (rem) {
        s += a3.x + a3.y + a3.z + a3.w;
        sq = fmaf(a3.x, a3.x, sq); sq = fmaf(a3.y, a3.y, sq);
        sq = fmaf(a3.z, a3.z, sq); sq = fmaf(a3.w, a3.w, sq);
    }

    // ---- Warp reduce partials, one barrier ----
    #pragma unroll
    for (int o = 16; o > 0; o >>= 1) {
        s  += __shfl_xor_sync(0xffffffffu, s,  o);
        sq += __shfl_xor_sync(0xffffffffu, sq, o);
    }
    if (lane == 0) { ps[wid] = s; psq[wid] = sq; }
    __syncthreads();

    // ---- Every thread: total sums -> mean/std ----
    float ts = 0.0f, tsq = 0.0f;
    #pragma unroll
    for (int i = 0; i < 8; i++) { ts += ps[i]; tsq += psq[i]; }

    const float n = (float)HW;
    const float mean = ts / n;
    float var = (tsq - n * mean * mean) / (n - 1.0f);
    var = fmaxf(var, 0.0f);
    const float std = sqrtf(var + EPS);

    // ---- Lane-parallel MLPs within each warp ----
    // lane < 16: hidden unit `lane` of the mean-MLP
    // lane >= 16: hidden unit `lane-16` of the std-MLP
    const int  j = lane & 15;
    const bool is_m = (lane < 16);
    const float* __restrict__ W1 = is_m ? W1m : W1s;
    const float* __restrict__ B1 = is_m ? b1m : b1s;
    const float* __restrict__ W2 = is_m ? W2m : W2s;
    const float* __restrict__ B2 = is_m ? b2m : b2s;

    float h = fmaf(__ldg(W1 + 2 * j), mean,
              fmaf(__ldg(W1 + 2 * j + 1), std, __ldg(B1 + j)));
    h = fmaxf(h, 0.0f);
    float p = __ldg(W2 + j) * h;

    // reduce within each 16-lane group (xor offsets < 16 keep groups apart)
    #pragma unroll
    for (int o = 8; o > 0; o >>= 1)
        p += __shfl_xor_sync(0xffffffffu, p, o);

    float z = p + __ldg(B2);
    float sig = 1.0f / (1.0f + __expf(-z));

    const float mean_w = __shfl_sync(0xffffffffu, sig, 0);
    const float std_w  = __shfl_sync(0xffffffffu, sig, 16);

    const float alpha = std_w;
    const float beta  = mean * (mean_w - std_w);

    // ---- Transform registers, streaming store ----
    float4 r;
    r.x = fmaf(a0.x, alpha, beta);
    r.y = fmaf(a0.y, alpha, beta);
    r.z = fmaf(a0.z, alpha, beta);
    r.w = fmaf(a0.w, alpha, beta);
    __stcs(orow + t, r);
    r.x = fmaf(a1.x, alpha, beta);
    r.y = fmaf(a1.y, alpha, beta);
    r.z = fmaf(a1.z, alpha, beta);
    r.w = fmaf(a1.w, alpha, beta);
    __stcs(orow + t + 256, r);
    r.x = fmaf(a2.x, alpha, beta);
    r.y = fmaf(a2.y, alpha, beta);
    r.z = fmaf(a2.z, alpha, beta);
    r.w = fmaf(a2.w, alpha, beta);
    __stcs(orow + t + 512, r);
    if (rem) {
        r.x = fmaf(a3.x, alpha, beta);
        r.y = fmaf(a3.y, alpha, beta);
        r.z = fmaf(a3.z, alpha, beta);
        r.w = fmaf(a3.w, alpha, beta);
        __stcs(orow + 768 + t, r);
    }
}

extern "C" void kernel_launch(void* const* d_in, const int* in_sizes, int n_in,
                              void* d_out, int out_size) {
    const float4* x  = (const float4*)d_in[0];
    const float* W1m = (const float*)d_in[1];
    const float* b1m = (const float*)d_in[2];
    const float* W2m = (const float*)d_in[3];
    const float* b2m = (const float*)d_in[4];
    const float* W1s = (const float*)d_in[5];
    const float* b1s = (const float*)d_in[6];
    const float* W2s = (const float*)d_in[7];
    const float* b2s = (const float*)d_in[8];
    float4* out = (float4*)d_out;

    const int rows = 32 * 256;  // B * C = 8192 CTAs, one row each
    selfnorm_kernel<<<rows, NTHREADS>>>(x, W1m, b1m, W2m, b2m,
                                        W1s, b1s, W2s, b2s, out);
}